// round 5
// baseline (speedup 1.0000x reference)
#include <cuda_runtime.h>

#define BH 64
#define SEQ 8192
#define D 64
#define SPLITS 16
#define RPS (SEQ / SPLITS)       // 512 rows per split
#define CHUNK 16
#define NCH (RPS / CHUNK)        // 32 chunks
#define PART_STRIDE (D * D + D)  // numer[4096] + z[64]

__device__ float g_part[BH * SPLITS * PART_STRIDE];  // ~17 MB scratch
__device__ float g_ctx[BH * D * D];

typedef unsigned long long ull;

__device__ __forceinline__ void fma2(ull& acc, ull a, ull b) {
    asm("fma.rn.f32x2 %0, %1, %2, %0;" : "+l"(acc) : "l"(a), "l"(b));
}
__device__ __forceinline__ void unpack2(ull v, float& x, float& y) {
    asm("mov.b64 {%0, %1}, %2;" : "=f"(x), "=f"(y) : "l"(v));
}

// ================= Kernel 1: partial context  exp(K)^T @ V  =================
// grid (BH, SPLITS), 128 threads. 4x8 microtile per thread (d x e).
// a-operand: exp(k) duplicated pairs at permuted index pi(d)=((d&3)<<4)|(d>>2)
// (conflict-free dup store); B-operand: v natural consecutive pairs.
__global__ void __launch_bounds__(128) ctx_partial_kernel(
    const float* __restrict__ k, const float* __restrict__ v) {
    const int head = blockIdx.x, split = blockIdx.y;
    const float* kb = k + (size_t)head * SEQ * D + (size_t)split * RPS * D;
    const float* vb = v + (size_t)head * SEQ * D + (size_t)split * RPS * D;

    __shared__ __align__(16) float ek2[2][CHUNK][2 * D];  // 16 KB dup pairs
    __shared__ __align__(16) float vv[2][CHUNK][D];       // 8 KB

    const int tid = threadIdx.x;
    const int tx = tid & 7;    // e-group of 8
    const int ty = tid >> 3;   // d-group of 4 (0..15)
    const int c16 = tid & 15;  // staging col group
    const int kr = tid >> 4;   // staging row (kr, kr+8)

    ull acc[4][4];
#pragma unroll
    for (int i = 0; i < 4; i++)
#pragma unroll
        for (int j = 0; j < 4; j++) acc[i][j] = 0ULL;
    float zacc = 0.0f;

    float4 kreg[2], vreg[2];
#pragma unroll
    for (int s = 0; s < 2; s++) {
        kreg[s] = *(const float4*)&kb[(kr + 8 * s) * D + c16 * 4];
        vreg[s] = *(const float4*)&vb[(kr + 8 * s) * D + c16 * 4];
    }
    // stage chunk 0 -> buf 0
#pragma unroll
    for (int s = 0; s < 2; s++) {
        const int row = kr + 8 * s;
        float2 pp;
        pp.x = pp.y = __expf(kreg[s].x); *(float2*)&ek2[0][row][2 * (0 * 16 + c16)] = pp;
        pp.x = pp.y = __expf(kreg[s].y); *(float2*)&ek2[0][row][2 * (1 * 16 + c16)] = pp;
        pp.x = pp.y = __expf(kreg[s].z); *(float2*)&ek2[0][row][2 * (2 * 16 + c16)] = pp;
        pp.x = pp.y = __expf(kreg[s].w); *(float2*)&ek2[0][row][2 * (3 * 16 + c16)] = pp;
        *(float4*)&vv[0][row][c16 * 4] = vreg[s];
    }
    __syncthreads();

    for (int c = 0; c < NCH; c++) {
        const int p = c & 1;
        if (c + 1 < NCH) {
#pragma unroll
            for (int s = 0; s < 2; s++) {
                kreg[s] = *(const float4*)&kb[(c + 1) * CHUNK * D + (kr + 8 * s) * D + c16 * 4];
                vreg[s] = *(const float4*)&vb[(c + 1) * CHUNK * D + (kr + 8 * s) * D + c16 * 4];
            }
        }
#pragma unroll
        for (int r = 0; r < CHUNK; r++) {
            ulonglong2 B0 = *(const ulonglong2*)&vv[p][r][tx * 8];
            ulonglong2 B1 = *(const ulonglong2*)&vv[p][r][tx * 8 + 4];
#pragma unroll
            for (int i = 0; i < 4; i++) {
                ull a = *(const ull*)&ek2[p][r][2 * ((i << 4) | ty)];
                fma2(acc[i][0], a, B0.x);
                fma2(acc[i][1], a, B0.y);
                fma2(acc[i][2], a, B1.x);
                fma2(acc[i][3], a, B1.y);
            }
        }
        if (tid < D) {
            const int g2 = 2 * (((tid & 3) << 4) | (tid >> 2));
#pragma unroll
            for (int r = 0; r < CHUNK; r++) zacc += ek2[p][r][g2];
        }
        if (c + 1 < NCH) {
            const int b = p ^ 1;
#pragma unroll
            for (int s = 0; s < 2; s++) {
                const int row = kr + 8 * s;
                float2 pp;
                pp.x = pp.y = __expf(kreg[s].x); *(float2*)&ek2[b][row][2 * (0 * 16 + c16)] = pp;
                pp.x = pp.y = __expf(kreg[s].y); *(float2*)&ek2[b][row][2 * (1 * 16 + c16)] = pp;
                pp.x = pp.y = __expf(kreg[s].z); *(float2*)&ek2[b][row][2 * (2 * 16 + c16)] = pp;
                pp.x = pp.y = __expf(kreg[s].w); *(float2*)&ek2[b][row][2 * (3 * 16 + c16)] = pp;
                *(float4*)&vv[b][row][c16 * 4] = vreg[s];
            }
        }
        __syncthreads();
    }

    float* np = g_part + (size_t)(head * SPLITS + split) * PART_STRIDE;
#pragma unroll
    for (int i = 0; i < 4; i++) {
        const int d = ty * 4 + i;
        float x0, x1, x2, x3, x4, x5, x6, x7;
        unpack2(acc[i][0], x0, x1);
        unpack2(acc[i][1], x2, x3);
        unpack2(acc[i][2], x4, x5);
        unpack2(acc[i][3], x6, x7);
        *(float4*)&np[d * D + tx * 8]     = make_float4(x0, x1, x2, x3);
        *(float4*)&np[d * D + tx * 8 + 4] = make_float4(x4, x5, x6, x7);
    }
    if (tid < D) np[D * D + tid] = zacc;
}

// ================= Kernel 2: reduce splits + normalize -> g_ctx =============
__global__ void __launch_bounds__(256) reduce_ctx_kernel() {
    const int head = blockIdx.x;
    const int tid = threadIdx.x;
    __shared__ float zs[D];
    const float* pb = g_part + (size_t)head * SPLITS * PART_STRIDE;

    if (tid < D) {
        float s = 0.0f;
#pragma unroll
        for (int sp = 0; sp < SPLITS; sp++) s += pb[sp * PART_STRIDE + D * D + tid];
        zs[tid] = 1.0f / s;
    }
    __syncthreads();

    const int i0 = blockIdx.y * 1024;
    for (int i = i0 + tid; i < i0 + 1024; i += 256) {
        float s = 0.0f;
#pragma unroll
        for (int sp = 0; sp < SPLITS; sp++) s += pb[sp * PART_STRIDE + i];
        g_ctx[head * D * D + i] = s * zs[i >> 6];
    }
}

// ================= Kernel 3: out = (softmax_ch(q)/8) @ ctx ==================
// grid (BH, 64), 128 threads, 2 row-tiles of 64 per CTA. 4x8 microtile.
// Dynamic smem: ctx[64][68] | pT2[64][128] (dup pairs) | ssum[64]
#define QTILES 2
#define CTX_LD 68
__global__ void __launch_bounds__(128) out_kernel(
    const float* __restrict__ q, float* __restrict__ out) {
    extern __shared__ __align__(16) float sm[];
    float* ctx  = sm;                      // 64*68
    float* pT2  = sm + D * CTX_LD;         // 64*128
    float* ssum = pT2 + D * 2 * D;         // 64

    const int head = blockIdx.x;
    const int tile0 = blockIdx.y * QTILES;
    const int tid = threadIdx.x;
    const int tx = tid & 7;    // e-group of 8
    const int ty = tid >> 3;   // row-group of 4 (0..15)

    // stage ctx for this head
    const float* gc = g_ctx + (size_t)head * D * D;
    for (int i = tid; i < (D * D) / 4; i += 128) {
        int d = i >> 4, e4 = (i & 15) << 2;
        *(float4*)&ctx[d * CTX_LD + e4] = *(const float4*)&gc[d * D + e4];
    }

    const float* qh = q + (size_t)head * SEQ * D;
    float4 qreg[8];
#pragma unroll
    for (int it = 0; it < 8; it++) {
        int i = tid + it * 128;
        qreg[it] = *(const float4*)&qh[(size_t)tile0 * 64 * D + (i >> 4) * D + ((i & 15) << 2)];
    }
    __syncthreads();

    for (int t = 0; t < QTILES; t++) {
        // ---- stage exp(q) dup pairs + row sums via shfl ----
#pragma unroll
        for (int it = 0; it < 8; it++) {
            int i = tid + it * 128;
            int r = i >> 4;       // row 0..63
            int cc = i & 15;      // col group; d = 4*cc+j, h(d) = cc ^ (j<<2)
            float e0 = __expf(qreg[it].x), e1 = __expf(qreg[it].y);
            float e2 = __expf(qreg[it].z), e3 = __expf(qreg[it].w);
            float2 pp;
            pp.x = pp.y = e0; *(float2*)&pT2[(4 * cc + 0) * 2 * D + 2 * (r ^ (cc ^ 0))]  = pp;
            pp.x = pp.y = e1; *(float2*)&pT2[(4 * cc + 1) * 2 * D + 2 * (r ^ (cc ^ 4))]  = pp;
            pp.x = pp.y = e2; *(float2*)&pT2[(4 * cc + 2) * 2 * D + 2 * (r ^ (cc ^ 8))]  = pp;
            pp.x = pp.y = e3; *(float2*)&pT2[(4 * cc + 3) * 2 * D + 2 * (r ^ (cc ^ 12))] = pp;
            float part = (e0 + e1) + (e2 + e3);
            part += __shfl_xor_sync(0xffffffffu, part, 8);
            part += __shfl_xor_sync(0xffffffffu, part, 4);
            part += __shfl_xor_sync(0xffffffffu, part, 2);
            part += __shfl_xor_sync(0xffffffffu, part, 1);
            if (cc == 0) ssum[r] = part;
        }
        __syncthreads();

        // prefetch next tile
        if (t + 1 < QTILES) {
#pragma unroll
            for (int it = 0; it < 8; it++) {
                int i = tid + it * 128;
                qreg[it] = *(const float4*)&qh[(size_t)(tile0 + t + 1) * 64 * D +
                                               (i >> 4) * D + ((i & 15) << 2)];
            }
        }

        // ---- compute: out[r,e] = sum_d p[r,d]*ctx[d,e], 4 rows x 8 e ----
        ull acc[4][4];
#pragma unroll
        for (int i = 0; i < 4; i++)
#pragma unroll
            for (int j = 0; j < 4; j++) acc[i][j] = 0ULL;

#pragma unroll
        for (int d = 0; d < D; d++) {
            const int h = ((d >> 2) & 15) ^ ((d & 3) << 2);
            ulonglong2 B0 = *(const ulonglong2*)&ctx[d * CTX_LD + tx * 8];
            ulonglong2 B1 = *(const ulonglong2*)&ctx[d * CTX_LD + tx * 8 + 4];
#pragma unroll
            for (int i = 0; i < 4; i++) {
                ull a = *(const ull*)&pT2[d * 2 * D + 2 * ((ty * 4 + i) ^ h)];
                fma2(acc[i][0], a, B0.x);
                fma2(acc[i][1], a, B0.y);
                fma2(acc[i][2], a, B1.x);
                fma2(acc[i][3], a, B1.y);
            }
        }

        // ---- epilogue ----
        float* ob = out + (size_t)head * SEQ * D + (size_t)(tile0 + t) * 64 * D;
#pragma unroll
        for (int i = 0; i < 4; i++) {
            const int r = ty * 4 + i;
            const float f = 0.125f / ssum[r];
            float x0, x1, x2, x3, x4, x5, x6, x7;
            unpack2(acc[i][0], x0, x1);
            unpack2(acc[i][1], x2, x3);
            unpack2(acc[i][2], x4, x5);
            unpack2(acc[i][3], x6, x7);
            *(float4*)&ob[r * D + tx * 8]     = make_float4(x0 * f, x1 * f, x2 * f, x3 * f);
            *(float4*)&ob[r * D + tx * 8 + 4] = make_float4(x4 * f, x5 * f, x6 * f, x7 * f);
        }
        __syncthreads();
    }
}

// ================= launch =================
extern "C" void kernel_launch(void* const* d_in, const int* in_sizes, int n_in,
                              void* d_out, int out_size) {
    const float* q = (const float*)d_in[0];
    const float* k = (const float*)d_in[1];
    const float* v = (const float*)d_in[2];
    float* out = (float*)d_out;
    (void)in_sizes; (void)n_in; (void)out_size;

    const int k3_smem = (D * CTX_LD + D * 2 * D + D) * (int)sizeof(float);  // ~50.4 KB
    static int attr_set = 0;
    if (!attr_set) {  // idempotent host-side attribute; not a stream op
        cudaFuncSetAttribute(out_kernel, cudaFuncAttributeMaxDynamicSharedMemorySize, k3_smem);
        attr_set = 1;
    }

    ctx_partial_kernel<<<dim3(BH, SPLITS), 128>>>(k, v);
    reduce_ctx_kernel<<<dim3(BH, 4), 256>>>();
    out_kernel<<<dim3(BH, SEQ / 64 / QTILES), 128, k3_smem>>>(q, out);
}

// round 7
// speedup vs baseline: 1.2415x; 1.2415x over previous
#include <cuda_runtime.h>
#include <cuda_bf16.h>
#include <cstdint>

#define BH 64
#define SEQ 8192
#define D 64
#define SPLITS 16
#define RPS (SEQ / SPLITS)      // 512
#define K1CH 32
#define K1NCH (RPS / K1CH)      // 16
#define PART_STRIDE (D * D + D)

__device__ float g_part[BH * SPLITS * PART_STRIDE];
__device__ float g_ctx[BH * D * D];

__device__ __forceinline__ uint32_t packbf(float x, float y) {
    __nv_bfloat162 t = __floats2bfloat162_rn(x, y);
    return *reinterpret_cast<uint32_t*>(&t);
}
__device__ __forceinline__ void hilo(float x, float& h, float& l) {
    h = __bfloat162float(__float2bfloat16(x));
    l = x - h;
}
// D += A*B, m16n8k16 bf16 -> f32
__device__ __forceinline__ void mma16816(float* c, uint32_t a0, uint32_t a1,
                                         uint32_t a2, uint32_t a3,
                                         uint32_t b0, uint32_t b1) {
    asm volatile(
        "mma.sync.aligned.m16n8k16.row.col.f32.bf16.bf16.f32 "
        "{%0,%1,%2,%3}, {%4,%5,%6,%7}, {%8,%9}, {%0,%1,%2,%3};"
        : "+f"(c[0]), "+f"(c[1]), "+f"(c[2]), "+f"(c[3])
        : "r"(a0), "r"(a1), "r"(a2), "r"(a3), "r"(b0), "r"(b1));
}

// ============== Kernel 1: partial context  exp(K)^T @ V  (HMMA) =============
// grid (BH, SPLITS), 128 threads = 4 warps. M=d(64), N=e(64), K=n(512 split).
// Pair arrays: ap[d][n2] = (ek[2n2][d], ek[2n2+1][d]) bf16x2 (hi/lo);
//              bp[e][n2] = (v [2n2][e], v [2n2+1][e]).
// Stride 18 words -> conflict-free fragment LDS (18*dg residues spaced >=4).
#define APS 18
__global__ void __launch_bounds__(128) ctx_partial_kernel(
    const float* __restrict__ k, const float* __restrict__ v) {
    __shared__ uint32_t apH[D * APS], apL[D * APS];
    __shared__ uint32_t bpH[D * APS], bpL[D * APS];

    const int head = blockIdx.x, split = blockIdx.y;
    const float* kb = k + (size_t)head * SEQ * D + (size_t)split * RPS * D;
    const float* vb = v + (size_t)head * SEQ * D + (size_t)split * RPS * D;

    const int tid = threadIdx.x;
    const int n2 = tid & 15;        // pair-row 0..15 (rows 2n2, 2n2+1)
    const int dg = tid >> 4;        // col group 0..7 (cols dg*8..dg*8+7)
    const int lane = tid & 31;
    const int wq = tid >> 5;        // warp: m-tile (16 d rows)
    const int g = lane >> 2, t4 = lane & 3;

    float acc[8][4];
#pragma unroll
    for (int i = 0; i < 8; i++)
#pragma unroll
        for (int j = 0; j < 4; j++) acc[i][j] = 0.0f;
    float zacc[8];
#pragma unroll
    for (int j = 0; j < 8; j++) zacc[j] = 0.0f;

    float4 k0, k0b, k1, k1b, v0, v0b, v1, v1b;

#define K1_LOAD(c)                                                        \
    {                                                                     \
        const float* kp = kb + (size_t)((c) * K1CH + 2 * n2) * D + dg * 8;\
        const float* vp = vb + (size_t)((c) * K1CH + 2 * n2) * D + dg * 8;\
        k0 = *(const float4*)kp;        k0b = *(const float4*)(kp + 4);   \
        k1 = *(const float4*)(kp + D);  k1b = *(const float4*)(kp + D + 4);\
        v0 = *(const float4*)vp;        v0b = *(const float4*)(vp + 4);   \
        v1 = *(const float4*)(vp + D);  v1b = *(const float4*)(vp + D + 4);\
    }

#define K1_STAGE()                                                          \
    {                                                                       \
        float e0, e1, h0, l0, h1, l1;                                       \
        _Pragma("unroll") for (int j = 0; j < 4; j++) {                     \
            const float ka = (&k0.x)[j], kc = (&k1.x)[j];                   \
            const int d = dg * 8 + j;                                       \
            e0 = __expf(ka); e1 = __expf(kc);                               \
            zacc[j] += e0 + e1;                                             \
            hilo(e0, h0, l0); hilo(e1, h1, l1);                             \
            apH[d * APS + n2] = packbf(h0, h1);                             \
            apL[d * APS + n2] = packbf(l0, l1);                             \
            const float va = (&v0.x)[j], vc = (&v1.x)[j];                   \
            hilo(va, h0, l0); hilo(vc, h1, l1);                             \
            bpH[d * APS + n2] = packbf(h0, h1);                             \
            bpL[d * APS + n2] = packbf(l0, l1);                             \
        }                                                                   \
        _Pragma("unroll") for (int j = 0; j < 4; j++) {                     \
            const float ka = (&k0b.x)[j], kc = (&k1b.x)[j];                 \
            const int d = dg * 8 + 4 + j;                                   \
            e0 = __expf(ka); e1 = __expf(kc);                               \
            zacc[4 + j] += e0 + e1;                                         \
            hilo(e0, h0, l0); hilo(e1, h1, l1);                             \
            apH[d * APS + n2] = packbf(h0, h1);                             \
            apL[d * APS + n2] = packbf(l0, l1);                             \
            const float va = (&v0b.x)[j], vc = (&v1b.x)[j];                 \
            hilo(va, h0, l0); hilo(vc, h1, l1);                             \
            bpH[d * APS + n2] = packbf(h0, h1);                             \
            bpL[d * APS + n2] = packbf(l0, l1);                             \
        }                                                                   \
    }

    K1_LOAD(0);
    K1_STAGE();
    __syncthreads();

    for (int c = 0; c < K1NCH; c++) {
        if (c + 1 < K1NCH) K1_LOAD(c + 1);
#pragma unroll
        for (int ks = 0; ks < 2; ks++) {
            const int koff = ks * 8;
            uint32_t ah[4], al[4];
            const int m0 = wq * 16 + g;
            ah[0] = apH[m0 * APS + koff + t4];
            ah[1] = apH[(m0 + 8) * APS + koff + t4];
            ah[2] = apH[m0 * APS + koff + 4 + t4];
            ah[3] = apH[(m0 + 8) * APS + koff + 4 + t4];
            al[0] = apL[m0 * APS + koff + t4];
            al[1] = apL[(m0 + 8) * APS + koff + t4];
            al[2] = apL[m0 * APS + koff + 4 + t4];
            al[3] = apL[(m0 + 8) * APS + koff + 4 + t4];
#pragma unroll
            for (int nt = 0; nt < 8; nt++) {
                const int e0r = nt * 8 + g;
                uint32_t bh0 = bpH[e0r * APS + koff + t4];
                uint32_t bh1 = bpH[e0r * APS + koff + 4 + t4];
                uint32_t bl0 = bpL[e0r * APS + koff + t4];
                uint32_t bl1 = bpL[e0r * APS + koff + 4 + t4];
                mma16816(acc[nt], ah[0], ah[1], ah[2], ah[3], bh0, bh1);
                mma16816(acc[nt], ah[0], ah[1], ah[2], ah[3], bl0, bl1);
                mma16816(acc[nt], al[0], al[1], al[2], al[3], bh0, bh1);
            }
        }
        __syncthreads();
        if (c + 1 < K1NCH) {
            K1_STAGE();
            __syncthreads();
        }
    }

    float* np = g_part + (size_t)(head * SPLITS + split) * PART_STRIDE;
    const int d0 = wq * 16 + g;
#pragma unroll
    for (int nt = 0; nt < 8; nt++) {
        const int ec = nt * 8 + 2 * t4;
        *(float2*)&np[d0 * D + ec] = make_float2(acc[nt][0], acc[nt][1]);
        *(float2*)&np[(d0 + 8) * D + ec] = make_float2(acc[nt][2], acc[nt][3]);
    }
    // reduce z over the 16 n2-lanes sharing this dg (lanes 0-15 / 16-31)
#pragma unroll
    for (int m = 1; m < 16; m <<= 1)
#pragma unroll
        for (int j = 0; j < 8; j++)
            zacc[j] += __shfl_xor_sync(0xffffffffu, zacc[j], m);
    if (n2 == 0) {
#pragma unroll
        for (int j = 0; j < 8; j++) np[D * D + dg * 8 + j] = zacc[j];
    }
}

// ============== Kernel 2: reduce splits + normalize -> g_ctx ================
__global__ void __launch_bounds__(256) reduce_ctx_kernel() {
    const int head = blockIdx.x;
    const int tid = threadIdx.x;
    __shared__ float zs[D];
    const float* pb = g_part + (size_t)head * SPLITS * PART_STRIDE;

    if (tid < D) {
        float s = 0.0f;
#pragma unroll
        for (int sp = 0; sp < SPLITS; sp++) s += pb[sp * PART_STRIDE + D * D + tid];
        zs[tid] = 1.0f / s;
    }
    __syncthreads();

    const int i0 = blockIdx.y * 1024;
    for (int i = i0 + tid; i < i0 + 1024; i += 256) {
        float s = 0.0f;
#pragma unroll
        for (int sp = 0; sp < SPLITS; sp++) s += pb[sp * PART_STRIDE + i];
        g_ctx[head * D * D + i] = s * zs[i >> 6];
    }
}

// ============== Kernel 3: out = (softmax_ch(q)/8) @ ctx  (HMMA) =============
// grid (BH, 16), 128 threads, 4 tiles of 128 rows. M=row(128), N=e(64), K=d(64).
// ap[r][k2] = (exp(q[r][2k2]), exp(q[r][2k2+1])); bp[e][d2] = (ctx[2d2][e], ctx[2d2+1][e]).
#define K3_TILES 4
#define BPS 36
#define O_APH 0
#define O_APL (O_APH + 128 * BPS)   // 4608
#define O_BPH (O_APL + 128 * BPS)   // 9216
#define O_BPL (O_BPH + 64 * BPS)    // 11520
#define O_SSUM (O_BPL + 64 * BPS)   // 13824
#define K3_SMEM ((O_SSUM + 128) * 4)

__global__ void __launch_bounds__(128) out_kernel(
    const float* __restrict__ q, float* __restrict__ out) {
    extern __shared__ uint32_t sm3[];
    uint32_t* apH = sm3 + O_APH;
    uint32_t* apL = sm3 + O_APL;
    uint32_t* bpH = sm3 + O_BPH;
    uint32_t* bpL = sm3 + O_BPL;
    float* ssum = (float*)(sm3 + O_SSUM);

    const int tid = threadIdx.x;
    const int lane = tid & 31;
    const int wq = tid >> 5;
    const int g = lane >> 2, t4 = lane & 3;
    const int head = blockIdx.x;
    const int tb0 = blockIdx.y * K3_TILES;

    // stage B = ctx (hi/lo transposed pairs)
    const float* gc = g_ctx + (size_t)head * D * D;
    for (int i = tid; i < 64 * 32; i += 128) {
        const int e = i >> 5, d2 = i & 31;
        float c0 = gc[(2 * d2) * D + e];
        float c1 = gc[(2 * d2 + 1) * D + e];
        float h0, l0, h1, l1;
        hilo(c0, h0, l0);
        hilo(c1, h1, l1);
        bpH[e * BPS + d2] = packbf(h0, h1);
        bpL[e * BPS + d2] = packbf(l0, l1);
    }

    const float* qh = q + (size_t)head * SEQ * D;

    for (int t = 0; t < K3_TILES; t++) {
        const int row0 = (tb0 + t) * 128;
        // stage A = exp(q) pairs + inv row sums
#pragma unroll
        for (int it = 0; it < 16; it++) {
            const int i = it * 128 + tid;
            const int r = i >> 4, cg = i & 15;
            float4 qv = *(const float4*)&qh[(size_t)(row0 + r) * D + cg * 4];
            float e0 = __expf(qv.x), e1 = __expf(qv.y);
            float e2 = __expf(qv.z), e3 = __expf(qv.w);
            float h0, l0, h1, l1, h2, l2, h3, l3;
            hilo(e0, h0, l0); hilo(e1, h1, l1);
            hilo(e2, h2, l2); hilo(e3, h3, l3);
            apH[r * BPS + 2 * cg] = packbf(h0, h1);
            apH[r * BPS + 2 * cg + 1] = packbf(h2, h3);
            apL[r * BPS + 2 * cg] = packbf(l0, l1);
            apL[r * BPS + 2 * cg + 1] = packbf(l2, l3);
            float part = (e0 + e1) + (e2 + e3);
            part += __shfl_xor_sync(0xffffffffu, part, 8);
            part += __shfl_xor_sync(0xffffffffu, part, 4);
            part += __shfl_xor_sync(0xffffffffu, part, 2);
            part += __shfl_xor_sync(0xffffffffu, part, 1);
            if (cg == 0) ssum[r] = 0.125f / part;
        }
        __syncthreads();

        float acc[2][8][4];
#pragma unroll
        for (int mm = 0; mm < 2; mm++)
#pragma unroll
            for (int nt = 0; nt < 8; nt++)
#pragma unroll
                for (int j = 0; j < 4; j++) acc[mm][nt][j] = 0.0f;

#pragma unroll
        for (int ks = 0; ks < 4; ks++) {
            const int koff = ks * 8;
            uint32_t ah[2][4], al[2][4];
#pragma unroll
            for (int mm = 0; mm < 2; mm++) {
                const int mb = wq * 32 + mm * 16;
                ah[mm][0] = apH[(mb + g) * BPS + koff + t4];
                ah[mm][1] = apH[(mb + 8 + g) * BPS + koff + t4];
                ah[mm][2] = apH[(mb + g) * BPS + koff + 4 + t4];
                ah[mm][3] = apH[(mb + 8 + g) * BPS + koff + 4 + t4];
                al[mm][0] = apL[(mb + g) * BPS + koff + t4];
                al[mm][1] = apL[(mb + 8 + g) * BPS + koff + t4];
                al[mm][2] = apL[(mb + g) * BPS + koff + 4 + t4];
                al[mm][3] = apL[(mb + 8 + g) * BPS + koff + 4 + t4];
            }
#pragma unroll
            for (int nt = 0; nt < 8; nt++) {
                const int er = nt * 8 + g;
                uint32_t bh0 = bpH[er * BPS + koff + t4];
                uint32_t bh1 = bpH[er * BPS + koff + 4 + t4];
                uint32_t bl0 = bpL[er * BPS + koff + t4];
                uint32_t bl1 = bpL[er * BPS + koff + 4 + t4];
#pragma unroll
                for (int mm = 0; mm < 2; mm++) {
                    mma16816(acc[mm][nt], ah[mm][0], ah[mm][1], ah[mm][2], ah[mm][3], bh0, bh1);
                    mma16816(acc[mm][nt], ah[mm][0], ah[mm][1], ah[mm][2], ah[mm][3], bl0, bl1);
                    mma16816(acc[mm][nt], al[mm][0], al[mm][1], al[mm][2], al[mm][3], bh0, bh1);
                }
            }
        }

        float* ob = out + (size_t)head * SEQ * D + (size_t)row0 * D;
#pragma unroll
        for (int mm = 0; mm < 2; mm++) {
            const int r = wq * 32 + mm * 16 + g;
            const float f0 = ssum[r], f1 = ssum[r + 8];
#pragma unroll
            for (int nt = 0; nt < 8; nt++) {
                const int cc = nt * 8 + 2 * t4;
                *(float2*)&ob[r * D + cc] =
                    make_float2(acc[mm][nt][0] * f0, acc[mm][nt][1] * f0);
                *(float2*)&ob[(r + 8) * D + cc] =
                    make_float2(acc[mm][nt][2] * f1, acc[mm][nt][3] * f1);
            }
        }
        __syncthreads();
    }
}

// ================= launch =================
extern "C" void kernel_launch(void* const* d_in, const int* in_sizes, int n_in,
                              void* d_out, int out_size) {
    const float* q = (const float*)d_in[0];
    const float* k = (const float*)d_in[1];
    const float* v = (const float*)d_in[2];
    float* out = (float*)d_out;
    (void)in_sizes; (void)n_in; (void)out_size;

    static int attr_set = 0;
    if (!attr_set) {
        cudaFuncSetAttribute(out_kernel, cudaFuncAttributeMaxDynamicSharedMemorySize,
                             K3_SMEM);
        attr_set = 1;
    }

    ctx_partial_kernel<<<dim3(BH, SPLITS), 128>>>(k, v);
    reduce_ctx_kernel<<<dim3(BH, 4), 256>>>();
    out_kernel<<<dim3(BH, SEQ / 128 / K3_TILES), 128, K3_SMEM>>>(q, out);
}

// round 8
// speedup vs baseline: 1.5483x; 1.2471x over previous
#include <cuda_runtime.h>
#include <cuda_bf16.h>
#include <cstdint>

#define BH 64
#define SEQ 8192
#define D 64
#define SPLITS 16
#define RPS (SEQ / SPLITS)      // 512
#define K1CH 32
#define K1NCH (RPS / K1CH)      // 16
#define PART_STRIDE (D * D + D)

__device__ float g_part[BH * SPLITS * PART_STRIDE];
__device__ float g_ctx[BH * D * D];

__device__ __forceinline__ uint32_t packbf(float x, float y) {
    __nv_bfloat162 t = __floats2bfloat162_rn(x, y);
    return *reinterpret_cast<uint32_t*>(&t);
}
__device__ __forceinline__ void hilo(float x, float& h, float& l) {
    h = __bfloat162float(__float2bfloat16(x));
    l = x - h;
}
__device__ __forceinline__ void mma16816(float* c, uint32_t a0, uint32_t a1,
                                         uint32_t a2, uint32_t a3,
                                         uint32_t b0, uint32_t b1) {
    asm volatile(
        "mma.sync.aligned.m16n8k16.row.col.f32.bf16.bf16.f32 "
        "{%0,%1,%2,%3}, {%4,%5,%6,%7}, {%8,%9}, {%0,%1,%2,%3};"
        : "+f"(c[0]), "+f"(c[1]), "+f"(c[2]), "+f"(c[3])
        : "r"(a0), "r"(a1), "r"(a2), "r"(a3), "r"(b0), "r"(b1));
}
__device__ __forceinline__ void ldsm4(uint32_t& r0, uint32_t& r1, uint32_t& r2,
                                      uint32_t& r3, uint32_t a) {
    asm volatile("ldmatrix.sync.aligned.m8n8.x4.shared.b16 {%0,%1,%2,%3}, [%4];"
                 : "=r"(r0), "=r"(r1), "=r"(r2), "=r"(r3) : "r"(a));
}
__device__ __forceinline__ uint32_t smem_u32(const void* p) {
    uint32_t a;
    asm("{ .reg .u64 t; cvta.to.shared.u64 t, %1; cvt.u32.u64 %0, t; }"
        : "=r"(a) : "l"(p));
    return a;
}
// Swizzled pair-array byte offset: rows of 128B (32 bf16x2 pairs),
// chunk (16B) index XOR'd with row&7 -> conflict-free ldmatrix phases.
__device__ __forceinline__ int swz(int r, int p) {
    return r * 128 + ((((p >> 2) ^ (r & 7)) << 4)) + (p & 3) * 4;
}

// ============== Kernel 1: partial context  exp(K)^T @ V  (HMMA+LDSM) ========
// grid (BH, SPLITS), 128 threads = 4 warps. M=d(64), N=e(64), K=n(512).
__global__ void __launch_bounds__(128) ctx_partial_kernel(
    const float* __restrict__ k, const float* __restrict__ v) {
    __shared__ __align__(16) char apH[8192], apL[8192], bpH[8192], bpL[8192];

    const int head = blockIdx.x, split = blockIdx.y;
    const float* kb = k + (size_t)head * SEQ * D + (size_t)split * RPS * D;
    const float* vb = v + (size_t)head * SEQ * D + (size_t)split * RPS * D;

    const int tid = threadIdx.x;
    const int lane = tid & 31;
    const int wq = tid >> 5;
    const int n2 = tid & 15;       // staging pair-row (rows 2n2, 2n2+1)
    const int dg = tid >> 4;       // staging col group (8 d's)
    const int g = lane >> 2, t4 = lane & 3;

    // ldmatrix per-lane base offsets (A: m16 tile of warp; B: 16-row n-group)
    const int rowA = wq * 16 + (lane & 15);
    const int offA = rowA * 128 + (((lane >> 4) ^ (rowA & 7)) << 4);
    const int rowB = ((lane >> 4) << 3) + (lane & 7);
    const int offB = rowB * 128 + ((((lane >> 3) & 1) ^ (rowB & 7)) << 4);

    const uint32_t uApH = smem_u32(apH), uApL = smem_u32(apL);
    const uint32_t uBpH = smem_u32(bpH), uBpL = smem_u32(bpL);

    float acc[8][4];
#pragma unroll
    for (int i = 0; i < 8; i++)
#pragma unroll
        for (int j = 0; j < 4; j++) acc[i][j] = 0.0f;
    float zacc[8];
#pragma unroll
    for (int j = 0; j < 8; j++) zacc[j] = 0.0f;

    float4 k0, k0b, k1, k1b, v0, v0b, v1, v1b;

#define K1_LOAD(c)                                                          \
    {                                                                       \
        const float* kp = kb + (size_t)((c) * K1CH + 2 * n2) * D + dg * 8;  \
        const float* vp = vb + (size_t)((c) * K1CH + 2 * n2) * D + dg * 8;  \
        k0 = *(const float4*)kp;        k0b = *(const float4*)(kp + 4);     \
        k1 = *(const float4*)(kp + D);  k1b = *(const float4*)(kp + D + 4); \
        v0 = *(const float4*)vp;        v0b = *(const float4*)(vp + 4);     \
        v1 = *(const float4*)(vp + D);  v1b = *(const float4*)(vp + D + 4); \
    }

#define K1_STAGE()                                                          \
    do {                                                                    \
        _Pragma("unroll") for (int j = 0; j < 4; j++) {                     \
            const int d = dg * 8 + j;                                       \
            float e0 = __expf((&k0.x)[j]), e1 = __expf((&k1.x)[j]);         \
            zacc[j] += e0 + e1;                                             \
            float h0, l0, h1, l1;                                           \
            hilo(e0, h0, l0); hilo(e1, h1, l1);                             \
            *(uint32_t*)(apH + swz(d, n2)) = packbf(h0, h1);                \
            *(uint32_t*)(apL + swz(d, n2)) = packbf(l0, l1);                \
            hilo((&v0.x)[j], h0, l0); hilo((&v1.x)[j], h1, l1);             \
            *(uint32_t*)(bpH + swz(d, n2)) = packbf(h0, h1);                \
            *(uint32_t*)(bpL + swz(d, n2)) = packbf(l0, l1);                \
        }                                                                   \
        _Pragma("unroll") for (int j = 0; j < 4; j++) {                     \
            const int d = dg * 8 + 4 + j;                                   \
            float e0 = __expf((&k0b.x)[j]), e1 = __expf((&k1b.x)[j]);       \
            zacc[4 + j] += e0 + e1;                                         \
            float h0, l0, h1, l1;                                           \
            hilo(e0, h0, l0); hilo(e1, h1, l1);                             \
            *(uint32_t*)(apH + swz(d, n2)) = packbf(h0, h1);                \
            *(uint32_t*)(apL + swz(d, n2)) = packbf(l0, l1);                \
            hilo((&v0b.x)[j], h0, l0); hilo((&v1b.x)[j], h1, l1);           \
            *(uint32_t*)(bpH + swz(d, n2)) = packbf(h0, h1);                \
            *(uint32_t*)(bpL + swz(d, n2)) = packbf(l0, l1);                \
        }                                                                   \
    } while (0)

    K1_LOAD(0);
    K1_STAGE();
    __syncthreads();

    for (int c = 0; c < K1NCH; c++) {
        if (c + 1 < K1NCH) K1_LOAD(c + 1);
#pragma unroll
        for (int ks = 0; ks < 2; ks++) {
            const int x = ks << 5;
            uint32_t ah0, ah1, ah2, ah3, al0, al1, al2, al3;
            ldsm4(ah0, ah1, ah2, ah3, uApH + (offA ^ x));
            ldsm4(al0, al1, al2, al3, uApL + (offA ^ x));
#pragma unroll
            for (int nt2 = 0; nt2 < 4; nt2++) {
                uint32_t bh0, bh1, bh2, bh3, bl0, bl1, bl2, bl3;
                ldsm4(bh0, bh1, bh2, bh3, uBpH + nt2 * 2048 + (offB ^ x));
                ldsm4(bl0, bl1, bl2, bl3, uBpL + nt2 * 2048 + (offB ^ x));
                mma16816(acc[2 * nt2], ah0, ah1, ah2, ah3, bh0, bh1);
                mma16816(acc[2 * nt2], ah0, ah1, ah2, ah3, bl0, bl1);
                mma16816(acc[2 * nt2], al0, al1, al2, al3, bh0, bh1);
                mma16816(acc[2 * nt2 + 1], ah0, ah1, ah2, ah3, bh2, bh3);
                mma16816(acc[2 * nt2 + 1], ah0, ah1, ah2, ah3, bl2, bl3);
                mma16816(acc[2 * nt2 + 1], al0, al1, al2, al3, bh2, bh3);
            }
        }
        __syncthreads();
        if (c + 1 < K1NCH) {
            K1_STAGE();
            __syncthreads();
        }
    }

    float* np = g_part + (size_t)(head * SPLITS + split) * PART_STRIDE;
    const int d0 = wq * 16 + g;
#pragma unroll
    for (int nt = 0; nt < 8; nt++) {
        const int ec = nt * 8 + 2 * t4;
        *(float2*)&np[d0 * D + ec] = make_float2(acc[nt][0], acc[nt][1]);
        *(float2*)&np[(d0 + 8) * D + ec] = make_float2(acc[nt][2], acc[nt][3]);
    }
#pragma unroll
    for (int m = 1; m < 16; m <<= 1)
#pragma unroll
        for (int j = 0; j < 8; j++)
            zacc[j] += __shfl_xor_sync(0xffffffffu, zacc[j], m);
    if (n2 == 0) {
#pragma unroll
        for (int j = 0; j < 8; j++) np[D * D + dg * 8 + j] = zacc[j];
    }
}

// ============== Kernel 2: reduce splits + normalize -> g_ctx ================
__global__ void __launch_bounds__(256) reduce_ctx_kernel() {
    const int head = blockIdx.x;
    const int tid = threadIdx.x;
    __shared__ float zs[D];
    const float* pb = g_part + (size_t)head * SPLITS * PART_STRIDE;

    if (tid < D) {
        float s = 0.0f;
#pragma unroll
        for (int sp = 0; sp < SPLITS; sp++) s += pb[sp * PART_STRIDE + D * D + tid];
        zs[tid] = 1.0f / s;
    }
    __syncthreads();

    const int i0 = blockIdx.y * 1024;
    for (int i = i0 + tid; i < i0 + 1024; i += 256) {
        float s = 0.0f;
#pragma unroll
        for (int sp = 0; sp < SPLITS; sp++) s += pb[sp * PART_STRIDE + i];
        g_ctx[head * D * D + i] = s * zs[i >> 6];
    }
}

// ============== Kernel 3: out = (softmax_ch(q)/8) @ ctx  (HMMA+LDSM) ========
// grid (BH, 16), 128 threads, 8 tiles of 64 rows. M=64/tile, N=64, K=64.
__global__ void __launch_bounds__(128) out_kernel(
    const float* __restrict__ q, float* __restrict__ out) {
    __shared__ __align__(16) char apH[8192], apL[8192], bpH[8192], bpL[8192];
    __shared__ float ssum[64];

    const int tid = threadIdx.x;
    const int lane = tid & 31;
    const int wq = tid >> 5;
    const int g = lane >> 2, t4 = lane & 3;
    const int head = blockIdx.x;
    const int tb0 = blockIdx.y * 8;

    // stage B = ctx hi/lo pairs (rows = e, pairs along d), swizzled
    const float* gc = g_ctx + (size_t)head * D * D;
    for (int i = tid; i < 64 * 32; i += 128) {
        const int e = i >> 5, d2 = i & 31;
        float c0 = gc[(2 * d2) * D + e];
        float c1 = gc[(2 * d2 + 1) * D + e];
        float h0, l0, h1, l1;
        hilo(c0, h0, l0);
        hilo(c1, h1, l1);
        *(uint32_t*)(bpH + swz(e, d2)) = packbf(h0, h1);
        *(uint32_t*)(bpL + swz(e, d2)) = packbf(l0, l1);
    }

    const int rowA = wq * 16 + (lane & 15);
    const int offA = rowA * 128 + (((lane >> 4) ^ (rowA & 7)) << 4);
    const int rowB = ((lane >> 4) << 3) + (lane & 7);
    const int offB = rowB * 128 + ((((lane >> 3) & 1) ^ (rowB & 7)) << 4);

    const uint32_t uApH = smem_u32(apH), uApL = smem_u32(apL);
    const uint32_t uBpH = smem_u32(bpH), uBpL = smem_u32(bpL);
    const float* qh = q + (size_t)head * SEQ * D;

    for (int t = 0; t < 8; t++) {
        const int row0 = (tb0 + t) * 64;
        // stage A = exp(q) hi/lo pairs + inv row sums
#pragma unroll
        for (int it = 0; it < 8; it++) {
            const int i = it * 128 + tid;
            const int r = i >> 4, cg = i & 15;
            float4 qv = *(const float4*)&qh[(size_t)(row0 + r) * D + cg * 4];
            float e0 = __expf(qv.x), e1 = __expf(qv.y);
            float e2 = __expf(qv.z), e3 = __expf(qv.w);
            float h0, l0, h1, l1, h2, l2, h3, l3;
            hilo(e0, h0, l0); hilo(e1, h1, l1);
            hilo(e2, h2, l2); hilo(e3, h3, l3);
            // pairs 2cg, 2cg+1 share one 16B chunk -> STS.64
            const int bo = r * 128 + ((((cg >> 1) ^ (r & 7)) << 4)) + (cg & 1) * 8;
            *(uint2*)(apH + bo) = make_uint2(packbf(h0, h1), packbf(h2, h3));
            *(uint2*)(apL + bo) = make_uint2(packbf(l0, l1), packbf(l2, l3));
            float part = (e0 + e1) + (e2 + e3);
            part += __shfl_xor_sync(0xffffffffu, part, 8);
            part += __shfl_xor_sync(0xffffffffu, part, 4);
            part += __shfl_xor_sync(0xffffffffu, part, 2);
            part += __shfl_xor_sync(0xffffffffu, part, 1);
            if (cg == 0) ssum[r] = 0.125f / part;
        }
        __syncthreads();

        float acc[8][4];
#pragma unroll
        for (int i = 0; i < 8; i++)
#pragma unroll
            for (int j = 0; j < 4; j++) acc[i][j] = 0.0f;

#pragma unroll
        for (int ks = 0; ks < 4; ks++) {
            const int x = ks << 5;
            uint32_t ah0, ah1, ah2, ah3, al0, al1, al2, al3;
            ldsm4(ah0, ah1, ah2, ah3, uApH + (offA ^ x));
            ldsm4(al0, al1, al2, al3, uApL + (offA ^ x));
#pragma unroll
            for (int nt2 = 0; nt2 < 4; nt2++) {
                uint32_t bh0, bh1, bh2, bh3, bl0, bl1, bl2, bl3;
                ldsm4(bh0, bh1, bh2, bh3, uBpH + nt2 * 2048 + (offB ^ x));
                ldsm4(bl0, bl1, bl2, bl3, uBpL + nt2 * 2048 + (offB ^ x));
                mma16816(acc[2 * nt2], ah0, ah1, ah2, ah3, bh0, bh1);
                mma16816(acc[2 * nt2], ah0, ah1, ah2, ah3, bl0, bl1);
                mma16816(acc[2 * nt2], al0, al1, al2, al3, bh0, bh1);
                mma16816(acc[2 * nt2 + 1], ah0, ah1, ah2, ah3, bh2, bh3);
                mma16816(acc[2 * nt2 + 1], ah0, ah1, ah2, ah3, bl2, bl3);
                mma16816(acc[2 * nt2 + 1], al0, al1, al2, al3, bh2, bh3);
            }
        }

        float* ob = out + (size_t)head * SEQ * D + (size_t)row0 * D;
        const int r0 = wq * 16 + g;
        const float f0 = ssum[r0], f1 = ssum[r0 + 8];
#pragma unroll
        for (int nt = 0; nt < 8; nt++) {
            const int cc = nt * 8 + 2 * t4;
            *(float2*)&ob[r0 * D + cc] =
                make_float2(acc[nt][0] * f0, acc[nt][1] * f0);
            *(float2*)&ob[(r0 + 8) * D + cc] =
                make_float2(acc[nt][2] * f1, acc[nt][3] * f1);
        }
        __syncthreads();
    }
}

// ================= launch =================
extern "C" void kernel_launch(void* const* d_in, const int* in_sizes, int n_in,
                              void* d_out, int out_size) {
    const float* q = (const float*)d_in[0];
    const float* k = (const float*)d_in[1];
    const float* v = (const float*)d_in[2];
    float* out = (float*)d_out;
    (void)in_sizes; (void)n_in; (void)out_size;

    ctx_partial_kernel<<<dim3(BH, SPLITS), 128>>>(k, v);
    reduce_ctx_kernel<<<dim3(BH, 4), 256>>>();
    out_kernel<<<dim3(BH, 16), 128>>>(q, out);
}

// round 9
// speedup vs baseline: 2.0351x; 1.3144x over previous
#include <cuda_runtime.h>
#include <cuda_bf16.h>
#include <cstdint>

#define BH 64
#define SEQ 8192
#define D 64
#define SPLITS 16
#define RPS (SEQ / SPLITS)      // 512
#define K1CH 32
#define K1NCH (RPS / K1CH)      // 16
#define PART_STRIDE (D * D + D)

__device__ float g_part[BH * SPLITS * PART_STRIDE];
__device__ float g_ctx[BH * D * D];

__device__ __forceinline__ uint32_t tf32r(float x) {
    uint32_t r;
    asm("cvt.rna.tf32.f32 %0, %1;" : "=r"(r) : "f"(x));
    return r;
}
// m16n8k8 tf32: D += A*B
__device__ __forceinline__ void mma_tf32(float* c, const uint32_t* a,
                                         uint32_t b0, uint32_t b1) {
    asm volatile(
        "mma.sync.aligned.m16n8k8.row.col.f32.tf32.tf32.f32 "
        "{%0,%1,%2,%3}, {%4,%5,%6,%7}, {%8,%9}, {%0,%1,%2,%3};"
        : "+f"(c[0]), "+f"(c[1]), "+f"(c[2]), "+f"(c[3])
        : "r"(a[0]), "r"(a[1]), "r"(a[2]), "r"(a[3]), "r"(b0), "r"(b1));
}

// ============== Kernel 1: partial context  exp(K)^T @ V  (tf32 HMMA) ========
// grid (BH, SPLITS), 128 threads = 4 warps (2x2 tiling, warp tile M32xN32).
// M=d(64), N=e(64), K=n(512 per split). Staged arrays [n][d/e] stride 72:
// fragment addr = t4*72 + g -> (8*t4+g) mod 32 distinct -> conflict-free.
__global__ void __launch_bounds__(128) ctx_partial_kernel(
    const float* __restrict__ k, const float* __restrict__ v) {
    __shared__ __align__(16) uint32_t ek[2][K1CH * 72];  // 18 KB
    __shared__ __align__(16) uint32_t vv[2][K1CH * 72];  // 18 KB
    __shared__ float zred[8][64];

    const int head = blockIdx.x, split = blockIdx.y;
    const float* kb = k + (size_t)head * SEQ * D + (size_t)split * RPS * D;
    const float* vb = v + (size_t)head * SEQ * D + (size_t)split * RPS * D;

    const int tid = threadIdx.x;
    const int lane = tid & 31;
    const int wq = tid >> 5;
    const int g = lane >> 2, t4 = lane & 3;
    const int wm = wq & 1, wn = wq >> 1;
    const int sr = tid >> 4;        // staging row group 0..7
    const int c4 = (tid & 15) * 4;  // staging col (constant per thread)

    float acc[2][4][4];
#pragma unroll
    for (int i = 0; i < 2; i++)
#pragma unroll
        for (int j = 0; j < 4; j++)
#pragma unroll
            for (int l = 0; l < 4; l++) acc[i][j][l] = 0.0f;
    float zacc[4] = {0.0f, 0.0f, 0.0f, 0.0f};

    float4 kreg[4], vreg[4];

#define K1_LOAD(c)                                                           \
    {                                                                        \
        _Pragma("unroll") for (int s = 0; s < 4; s++) {                      \
            const int r = s * 8 + sr;                                        \
            kreg[s] = *(const float4*)&kb[(size_t)((c) * K1CH + r) * D + c4];\
            vreg[s] = *(const float4*)&vb[(size_t)((c) * K1CH + r) * D + c4];\
        }                                                                    \
    }

#define K1_STAGE(b)                                                          \
    do {                                                                     \
        _Pragma("unroll") for (int s = 0; s < 4; s++) {                      \
            const int r = s * 8 + sr;                                        \
            uint4 eu, vu;                                                    \
            eu.x = tf32r(__expf(kreg[s].x));                                 \
            eu.y = tf32r(__expf(kreg[s].y));                                 \
            eu.z = tf32r(__expf(kreg[s].z));                                 \
            eu.w = tf32r(__expf(kreg[s].w));                                 \
            zacc[0] += __uint_as_float(eu.x);                                \
            zacc[1] += __uint_as_float(eu.y);                                \
            zacc[2] += __uint_as_float(eu.z);                                \
            zacc[3] += __uint_as_float(eu.w);                                \
            vu.x = tf32r(vreg[s].x); vu.y = tf32r(vreg[s].y);                \
            vu.z = tf32r(vreg[s].z); vu.w = tf32r(vreg[s].w);                \
            *(uint4*)&ek[b][r * 72 + c4] = eu;                               \
            *(uint4*)&vv[b][r * 72 + c4] = vu;                               \
        }                                                                    \
    } while (0)

    K1_LOAD(0);
    K1_STAGE(0);
    __syncthreads();

    for (int c = 0; c < K1NCH; c++) {
        const int p = c & 1;
        if (c + 1 < K1NCH) K1_LOAD(c + 1);
#pragma unroll
        for (int ks = 0; ks < 4; ks++) {
            const int n0 = ks * 8;
            const int ra = (n0 + t4) * 72, rb = (n0 + 4 + t4) * 72;
            uint32_t A[2][4];
#pragma unroll
            for (int mt = 0; mt < 2; mt++) {
                const int dd = wm * 32 + mt * 16 + g;
                A[mt][0] = ek[p][ra + dd];
                A[mt][1] = ek[p][ra + dd + 8];
                A[mt][2] = ek[p][rb + dd];
                A[mt][3] = ek[p][rb + dd + 8];
            }
#pragma unroll
            for (int nt = 0; nt < 4; nt++) {
                const int ee = wn * 32 + nt * 8 + g;
                uint32_t b0 = vv[p][ra + ee];
                uint32_t b1 = vv[p][rb + ee];
                mma_tf32(acc[0][nt], A[0], b0, b1);
                mma_tf32(acc[1][nt], A[1], b0, b1);
            }
        }
        __syncthreads();
        if (c + 1 < K1NCH) {
            K1_STAGE(p ^ 1);
            __syncthreads();
        }
    }

    float* np = g_part + (size_t)(head * SPLITS + split) * PART_STRIDE;
#pragma unroll
    for (int mt = 0; mt < 2; mt++) {
        const int d0 = wm * 32 + mt * 16 + g;
#pragma unroll
        for (int nt = 0; nt < 4; nt++) {
            const int ee = wn * 32 + nt * 8 + 2 * t4;
            *(float2*)&np[d0 * D + ee] =
                make_float2(acc[mt][nt][0], acc[mt][nt][1]);
            *(float2*)&np[(d0 + 8) * D + ee] =
                make_float2(acc[mt][nt][2], acc[mt][nt][3]);
        }
    }
    // z reduction: thread holds cols c4..c4+3; 8 thread-groups share each col
#pragma unroll
    for (int j = 0; j < 4; j++) zred[sr][c4 + j] = zacc[j];
    __syncthreads();
    if (tid < 64) {
        float s = 0.0f;
#pragma unroll
        for (int t = 0; t < 8; t++) s += zred[t][tid];
        np[D * D + tid] = s;
    }
}

// ============== Kernel 2: reduce splits + normalize -> g_ctx ================
__global__ void __launch_bounds__(256) reduce_ctx_kernel() {
    const int head = blockIdx.x;
    const int tid = threadIdx.x;
    __shared__ float zs[D];
    const float* pb = g_part + (size_t)head * SPLITS * PART_STRIDE;

    if (tid < D) {
        float s = 0.0f;
#pragma unroll
        for (int sp = 0; sp < SPLITS; sp++) s += pb[sp * PART_STRIDE + D * D + tid];
        zs[tid] = 1.0f / s;
    }
    __syncthreads();

    const int i0 = blockIdx.y * 1024;
    for (int i = i0 + tid; i < i0 + 1024; i += 256) {
        float s = 0.0f;
#pragma unroll
        for (int sp = 0; sp < SPLITS; sp++) s += pb[sp * PART_STRIDE + i];
        g_ctx[head * D * D + i] = s * zs[i >> 6];
    }
}

// ============== Kernel 3: out = (softmax_ch(q)/8) @ ctx  (tf32 HMMA) ========
// grid (BH, 16), 128 threads, 8 tiles of 64 rows. M=64/tile, N=64, K=64.
// A = exp(q) staged [r][d] stride 68 (frag addr 4g+t4 distinct mod 32);
// B = ctx staged once [d][e] stride 72 (frag addr 8t4+g distinct mod 32).
__global__ void __launch_bounds__(128) out_kernel(
    const float* __restrict__ q, float* __restrict__ out) {
    __shared__ __align__(16) uint32_t aq[64 * 68];    // 17 KB
    __shared__ __align__(16) uint32_t ctxs[64 * 72];  // 18 KB
    __shared__ float ssum[64];

    const int tid = threadIdx.x;
    const int lane = tid & 31;
    const int wq = tid >> 5;
    const int g = lane >> 2, t4 = lane & 3;
    const int wm = wq & 1, wn = wq >> 1;
    const int sr = tid >> 4;
    const int c4 = (tid & 15) * 4;
    const int head = blockIdx.x;

    // stage B = ctx (tf32-rounded), natural [d][e] rows
    const float* gc = g_ctx + (size_t)head * D * D;
    for (int i = tid; i < 64 * 16; i += 128) {
        const int d = i >> 4, cg4 = (i & 15) * 4;
        float4 cv = *(const float4*)&gc[d * D + cg4];
        uint4 cu;
        cu.x = tf32r(cv.x); cu.y = tf32r(cv.y);
        cu.z = tf32r(cv.z); cu.w = tf32r(cv.w);
        *(uint4*)&ctxs[d * 72 + cg4] = cu;
    }

    const float* qh = q + (size_t)head * SEQ * D;

    for (int t = 0; t < 8; t++) {
        const int row0 = (blockIdx.y * 8 + t) * 64;
        // stage A = exp(q) + inv row sums
#pragma unroll
        for (int s = 0; s < 8; s++) {
            const int r = s * 8 + sr;
            float4 qv = *(const float4*)&qh[(size_t)(row0 + r) * D + c4];
            uint4 eu;
            eu.x = tf32r(__expf(qv.x));
            eu.y = tf32r(__expf(qv.y));
            eu.z = tf32r(__expf(qv.z));
            eu.w = tf32r(__expf(qv.w));
            *(uint4*)&aq[r * 68 + c4] = eu;
            float part = (__uint_as_float(eu.x) + __uint_as_float(eu.y)) +
                         (__uint_as_float(eu.z) + __uint_as_float(eu.w));
            part += __shfl_xor_sync(0xffffffffu, part, 8);
            part += __shfl_xor_sync(0xffffffffu, part, 4);
            part += __shfl_xor_sync(0xffffffffu, part, 2);
            part += __shfl_xor_sync(0xffffffffu, part, 1);
            if ((tid & 15) == 0) ssum[r] = 0.125f / part;
        }
        __syncthreads();

        float acc[2][4][4];
#pragma unroll
        for (int i = 0; i < 2; i++)
#pragma unroll
            for (int j = 0; j < 4; j++)
#pragma unroll
                for (int l = 0; l < 4; l++) acc[i][j][l] = 0.0f;

#pragma unroll
        for (int ks = 0; ks < 8; ks++) {
            const int d0 = ks * 8;
            uint32_t A[2][4];
#pragma unroll
            for (int mt = 0; mt < 2; mt++) {
                const int rb = wm * 32 + mt * 16;
                A[mt][0] = aq[(rb + g) * 68 + d0 + t4];
                A[mt][1] = aq[(rb + 8 + g) * 68 + d0 + t4];
                A[mt][2] = aq[(rb + g) * 68 + d0 + 4 + t4];
                A[mt][3] = aq[(rb + 8 + g) * 68 + d0 + 4 + t4];
            }
            const int ra = (d0 + t4) * 72, rbb = (d0 + 4 + t4) * 72;
#pragma unroll
            for (int nt = 0; nt < 4; nt++) {
                const int ee = wn * 32 + nt * 8 + g;
                uint32_t b0 = ctxs[ra + ee];
                uint32_t b1 = ctxs[rbb + ee];
                mma_tf32(acc[0][nt], A[0], b0, b1);
                mma_tf32(acc[1][nt], A[1], b0, b1);
            }
        }

        float* ob = out + (size_t)head * SEQ * D + (size_t)row0 * D;
#pragma unroll
        for (int mt = 0; mt < 2; mt++) {
            const int r0 = wm * 32 + mt * 16 + g;
            const float f0 = ssum[r0], f1 = ssum[r0 + 8];
#pragma unroll
            for (int nt = 0; nt < 4; nt++) {
                const int cc = wn * 32 + nt * 8 + 2 * t4;
                *(float2*)&ob[r0 * D + cc] =
                    make_float2(acc[mt][nt][0] * f0, acc[mt][nt][1] * f0);
                *(float2*)&ob[(r0 + 8) * D + cc] =
                    make_float2(acc[mt][nt][2] * f1, acc[mt][nt][3] * f1);
            }
        }
        __syncthreads();
    }
}

// ================= launch =================
extern "C" void kernel_launch(void* const* d_in, const int* in_sizes, int n_in,
                              void* d_out, int out_size) {
    const float* q = (const float*)d_in[0];
    const float* k = (const float*)d_in[1];
    const float* v = (const float*)d_in[2];
    float* out = (float*)d_out;
    (void)in_sizes; (void)n_in; (void)out_size;

    ctx_partial_kernel<<<dim3(BH, SPLITS), 128>>>(k, v);
    reduce_ctx_kernel<<<dim3(BH, 4), 256>>>();
    out_kernel<<<dim3(BH, 16), 128>>>(q, out);
}

// round 10
// speedup vs baseline: 2.7255x; 1.3393x over previous
#include <cuda_runtime.h>
#include <cuda_bf16.h>
#include <cstdint>

#define BH 64
#define SEQ 8192
#define D 64
#define SPLITS 16
#define RPS (SEQ / SPLITS)      // 512
#define K1CH 32
#define K1NCH (RPS / K1CH)      // 16
#define PART_STRIDE (D * D + D)

__device__ float g_part[BH * SPLITS * PART_STRIDE];
__device__ float g_ctx[BH * D * D];

__device__ __forceinline__ uint32_t tf32r(float x) {
    uint32_t r;
    asm("cvt.rna.tf32.f32 %0, %1;" : "=r"(r) : "f"(x));
    return r;
}
// m16n8k8 tf32: D += A*B
__device__ __forceinline__ void mma_tf32(float* c, const uint32_t* a,
                                         uint32_t b0, uint32_t b1) {
    asm volatile(
        "mma.sync.aligned.m16n8k8.row.col.f32.tf32.tf32.f32 "
        "{%0,%1,%2,%3}, {%4,%5,%6,%7}, {%8,%9}, {%0,%1,%2,%3};"
        : "+f"(c[0]), "+f"(c[1]), "+f"(c[2]), "+f"(c[3])
        : "r"(a[0]), "r"(a[1]), "r"(a[2]), "r"(a[3]), "r"(b0), "r"(b1));
}

// ============== Kernel 1: partial context  exp(K)^T @ V  (tf32 HMMA) ========
// grid (BH, SPLITS), 128 threads = 4 warps (2x2 tiling, warp tile M32xN32).
// M=d(64), N=e(64), K=n(512 per split). Staged arrays [n][d/e] stride 72:
// fragment addr = t4*72 + g -> (8*t4+g) mod 32 distinct -> conflict-free.
__global__ void __launch_bounds__(128) ctx_partial_kernel(
    const float* __restrict__ k, const float* __restrict__ v) {
    __shared__ __align__(16) uint32_t ek[2][K1CH * 72];  // 18 KB
    __shared__ __align__(16) uint32_t vv[2][K1CH * 72];  // 18 KB
    __shared__ float zred[8][64];

    const int head = blockIdx.x, split = blockIdx.y;
    const float* kb = k + (size_t)head * SEQ * D + (size_t)split * RPS * D;
    const float* vb = v + (size_t)head * SEQ * D + (size_t)split * RPS * D;

    const int tid = threadIdx.x;
    const int lane = tid & 31;
    const int wq = tid >> 5;
    const int g = lane >> 2, t4 = lane & 3;
    const int wm = wq & 1, wn = wq >> 1;
    const int sr = tid >> 4;        // staging row group 0..7
    const int c4 = (tid & 15) * 4;  // staging col (constant per thread)

    float acc[2][4][4];
#pragma unroll
    for (int i = 0; i < 2; i++)
#pragma unroll
        for (int j = 0; j < 4; j++)
#pragma unroll
            for (int l = 0; l < 4; l++) acc[i][j][l] = 0.0f;
    float zacc[4] = {0.0f, 0.0f, 0.0f, 0.0f};

    float4 kreg[4], vreg[4];

#define K1_LOAD(c)                                                           \
    {                                                                        \
        _Pragma("unroll") for (int s = 0; s < 4; s++) {                      \
            const int r = s * 8 + sr;                                        \
            kreg[s] = *(const float4*)&kb[(size_t)((c) * K1CH + r) * D + c4];\
            vreg[s] = *(const float4*)&vb[(size_t)((c) * K1CH + r) * D + c4];\
        }                                                                    \
    }

#define K1_STAGE(b)                                                          \
    do {                                                                     \
        _Pragma("unroll") for (int s = 0; s < 4; s++) {                      \
            const int r = s * 8 + sr;                                        \
            uint4 eu, vu;                                                    \
            eu.x = tf32r(__expf(kreg[s].x));                                 \
            eu.y = tf32r(__expf(kreg[s].y));                                 \
            eu.z = tf32r(__expf(kreg[s].z));                                 \
            eu.w = tf32r(__expf(kreg[s].w));                                 \
            zacc[0] += __uint_as_float(eu.x);                                \
            zacc[1] += __uint_as_float(eu.y);                                \
            zacc[2] += __uint_as_float(eu.z);                                \
            zacc[3] += __uint_as_float(eu.w);                                \
            vu.x = tf32r(vreg[s].x); vu.y = tf32r(vreg[s].y);                \
            vu.z = tf32r(vreg[s].z); vu.w = tf32r(vreg[s].w);                \
            *(uint4*)&ek[b][r * 72 + c4] = eu;                               \
            *(uint4*)&vv[b][r * 72 + c4] = vu;                               \
        }                                                                    \
    } while (0)

    K1_LOAD(0);
    K1_STAGE(0);
    __syncthreads();

    for (int c = 0; c < K1NCH; c++) {
        const int p = c & 1;
        if (c + 1 < K1NCH) K1_LOAD(c + 1);
#pragma unroll
        for (int ks = 0; ks < 4; ks++) {
            const int n0 = ks * 8;
            const int ra = (n0 + t4) * 72, rb = (n0 + 4 + t4) * 72;
            uint32_t A[2][4];
#pragma unroll
            for (int mt = 0; mt < 2; mt++) {
                const int dd = wm * 32 + mt * 16 + g;
                A[mt][0] = ek[p][ra + dd];
                A[mt][1] = ek[p][ra + dd + 8];
                A[mt][2] = ek[p][rb + dd];
                A[mt][3] = ek[p][rb + dd + 8];
            }
#pragma unroll
            for (int nt = 0; nt < 4; nt++) {
                const int ee = wn * 32 + nt * 8 + g;
                uint32_t b0 = vv[p][ra + ee];
                uint32_t b1 = vv[p][rb + ee];
                mma_tf32(acc[0][nt], A[0], b0, b1);
                mma_tf32(acc[1][nt], A[1], b0, b1);
            }
        }
        __syncthreads();
        if (c + 1 < K1NCH) {
            K1_STAGE(p ^ 1);
            __syncthreads();
        }
    }

    float* np = g_part + (size_t)(head * SPLITS + split) * PART_STRIDE;
#pragma unroll
    for (int mt = 0; mt < 2; mt++) {
        const int d0 = wm * 32 + mt * 16 + g;
#pragma unroll
        for (int nt = 0; nt < 4; nt++) {
            const int ee = wn * 32 + nt * 8 + 2 * t4;
            *(float2*)&np[d0 * D + ee] =
                make_float2(acc[mt][nt][0], acc[mt][nt][1]);
            *(float2*)&np[(d0 + 8) * D + ee] =
                make_float2(acc[mt][nt][2], acc[mt][nt][3]);
        }
    }
    // z reduction: thread holds cols c4..c4+3; 8 thread-groups share each col
#pragma unroll
    for (int j = 0; j < 4; j++) zred[sr][c4 + j] = zacc[j];
    __syncthreads();
    if (tid < 64) {
        float s = 0.0f;
#pragma unroll
        for (int t = 0; t < 8; t++) s += zred[t][tid];
        np[D * D + tid] = s;
    }
}

// ============== Kernel 2: reduce splits + normalize -> g_ctx ================
__global__ void __launch_bounds__(256) reduce_ctx_kernel() {
    const int head = blockIdx.x;
    const int tid = threadIdx.x;
    __shared__ float zs[D];
    const float* pb = g_part + (size_t)head * SPLITS * PART_STRIDE;

    if (tid < D) {
        float s = 0.0f;
#pragma unroll
        for (int sp = 0; sp < SPLITS; sp++) s += pb[sp * PART_STRIDE + D * D + tid];
        zs[tid] = 1.0f / s;
    }
    __syncthreads();

    const int i0 = blockIdx.y * 1024;
    for (int i = i0 + tid; i < i0 + 1024; i += 256) {
        float s = 0.0f;
#pragma unroll
        for (int sp = 0; sp < SPLITS; sp++) s += pb[sp * PART_STRIDE + i];
        g_ctx[head * D * D + i] = s * zs[i >> 6];
    }
}

// ============== Kernel 3: out = (softmax_ch(q)/8) @ ctx  (tf32 HMMA) ========
// grid (BH, 16), 128 threads, 8 tiles of 64 rows. M=64/tile, N=64, K=64.
// A = exp(q) staged [r][d] stride 68 (frag addr 4g+t4 distinct mod 32);
// B = ctx staged once [d][e] stride 72 (frag addr 8t4+g distinct mod 32).
// Next tile's q is register-prefetched during the current tile's MMAs.
__global__ void __launch_bounds__(128) out_kernel(
    const float* __restrict__ q, float* __restrict__ out) {
    __shared__ __align__(16) uint32_t aq[64 * 68];    // 17 KB
    __shared__ __align__(16) uint32_t ctxs[64 * 72];  // 18 KB
    __shared__ float ssum[64];

    const int tid = threadIdx.x;
    const int lane = tid & 31;
    const int wq = tid >> 5;
    const int g = lane >> 2, t4 = lane & 3;
    const int wm = wq & 1, wn = wq >> 1;
    const int sr = tid >> 4;
    const int c4 = (tid & 15) * 4;
    const int head = blockIdx.x;

    // stage B = ctx (tf32-rounded), natural [d][e] rows
    const float* gc = g_ctx + (size_t)head * D * D;
    for (int i = tid; i < 64 * 16; i += 128) {
        const int d = i >> 4, cg4 = (i & 15) * 4;
        float4 cv = *(const float4*)&gc[d * D + cg4];
        uint4 cu;
        cu.x = tf32r(cv.x); cu.y = tf32r(cv.y);
        cu.z = tf32r(cv.z); cu.w = tf32r(cv.w);
        *(uint4*)&ctxs[d * 72 + cg4] = cu;
    }

    const float* qh = q + (size_t)head * SEQ * D;

    // prefetch tile 0
    float4 qreg[8];
#pragma unroll
    for (int s = 0; s < 8; s++) {
        const int r = s * 8 + sr;
        qreg[s] = *(const float4*)&qh[(size_t)(blockIdx.y * 8) * 64 * D + (size_t)r * D + c4];
    }

    for (int t = 0; t < 8; t++) {
        const int row0 = (blockIdx.y * 8 + t) * 64;
        // stage A = exp(q) + inv row sums (from prefetched registers)
#pragma unroll
        for (int s = 0; s < 8; s++) {
            const int r = s * 8 + sr;
            uint4 eu;
            eu.x = tf32r(__expf(qreg[s].x));
            eu.y = tf32r(__expf(qreg[s].y));
            eu.z = tf32r(__expf(qreg[s].z));
            eu.w = tf32r(__expf(qreg[s].w));
            *(uint4*)&aq[r * 68 + c4] = eu;
            float part = (__uint_as_float(eu.x) + __uint_as_float(eu.y)) +
                         (__uint_as_float(eu.z) + __uint_as_float(eu.w));
            part += __shfl_xor_sync(0xffffffffu, part, 8);
            part += __shfl_xor_sync(0xffffffffu, part, 4);
            part += __shfl_xor_sync(0xffffffffu, part, 2);
            part += __shfl_xor_sync(0xffffffffu, part, 1);
            if ((tid & 15) == 0) ssum[r] = 0.125f / part;
        }
        __syncthreads();

        // issue next tile's LDGs now; they complete during the MMAs below
        if (t + 1 < 8) {
            const int nrow0 = row0 + 64;
#pragma unroll
            for (int s = 0; s < 8; s++) {
                const int r = s * 8 + sr;
                qreg[s] = *(const float4*)&qh[(size_t)(nrow0 + r) * D + c4];
            }
        }

        float acc[2][4][4];
#pragma unroll
        for (int i = 0; i < 2; i++)
#pragma unroll
            for (int j = 0; j < 4; j++)
#pragma unroll
                for (int l = 0; l < 4; l++) acc[i][j][l] = 0.0f;

#pragma unroll
        for (int ks = 0; ks < 8; ks++) {
            const int d0 = ks * 8;
            uint32_t A[2][4];
#pragma unroll
            for (int mt = 0; mt < 2; mt++) {
                const int rb = wm * 32 + mt * 16;
                A[mt][0] = aq[(rb + g) * 68 + d0 + t4];
                A[mt][1] = aq[(rb + 8 + g) * 68 + d0 + t4];
                A[mt][2] = aq[(rb + g) * 68 + d0 + 4 + t4];
                A[mt][3] = aq[(rb + 8 + g) * 68 + d0 + 4 + t4];
            }
            const int ra = (d0 + t4) * 72, rbb = (d0 + 4 + t4) * 72;
#pragma unroll
            for (int nt = 0; nt < 4; nt++) {
                const int ee = wn * 32 + nt * 8 + g;
                uint32_t b0 = ctxs[ra + ee];
                uint32_t b1 = ctxs[rbb + ee];
                mma_tf32(acc[0][nt], A[0], b0, b1);
                mma_tf32(acc[1][nt], A[1], b0, b1);
            }
        }

        float* ob = out + (size_t)head * SEQ * D + (size_t)row0 * D;
#pragma unroll
        for (int mt = 0; mt < 2; mt++) {
            const int r0 = wm * 32 + mt * 16 + g;
            const float f0 = ssum[r0], f1 = ssum[r0 + 8];
#pragma unroll
            for (int nt = 0; nt < 4; nt++) {
                const int cc = wn * 32 + nt * 8 + 2 * t4;
                *(float2*)&ob[r0 * D + cc] =
                    make_float2(acc[mt][nt][0] * f0, acc[mt][nt][1] * f0);
                *(float2*)&ob[(r0 + 8) * D + cc] =
                    make_float2(acc[mt][nt][2] * f1, acc[mt][nt][3] * f1);
            }
        }
        __syncthreads();
    }
}

// ================= launch =================
extern "C" void kernel_launch(void* const* d_in, const int* in_sizes, int n_in,
                              void* d_out, int out_size) {
    const float* q = (const float*)d_in[0];
    const float* k = (const float*)d_in[1];
    const float* v = (const float*)d_in[2];
    float* out = (float*)d_out;
    (void)in_sizes; (void)n_in; (void)out_size;

    ctx_partial_kernel<<<dim3(BH, SPLITS), 128>>>(k, v);
    reduce_ctx_kernel<<<dim3(BH, 4), 256>>>();
    out_kernel<<<dim3(BH, 16), 128>>>(q, out);
}